// round 9
// baseline (speedup 1.0000x reference)
#include <cuda_runtime.h>

// SMFNet B=2,N=8192,D=64,DV=64,M=3 — chord mask = diag + superdiag(wrap).
// out = S · V0 ;  V0 = X@Wg + bg ; S = product of three 2-banded chord mats:
//   out[i] = w0 V0[i] + w1 V0[i+1] + w2 V0[i+2] + w3 V0[i+3]   (wrap)
//   Am_j = X[j]·Wf[m][:,j] + bf[m][j],  Cm_j = X[j]·Wf[m][:,j+1] + bf[m][j+1]
// R9: Wg in smem, GEMM fully unrolled (imm-offset LDS only, no IMAD/LDG),
// 8col x 2row thread tiles with broadcast second row; A/C fully unrolled LDG.

#define Bc   2
#define Nc   8192
#define Dc   64
#define TROWS 16           // output rows per CTA -> 512 CTAs
#define XR    20           // row slots per batch (19 used)
#define RS    40           // total row slots (38 used)
#define PAD   68           // float4-aligned row stride (272B)
#define ACW   20
#define NTHREADS 256

typedef unsigned long long u64;

// smem (floats)
#define OFF_XS   0                      // RS*PAD = 2720
#define OFF_VS   (OFF_XS + RS*PAD)      // RS*PAD = 2720
#define OFF_WG   (OFF_VS + RS*PAD)      // 64*64  = 4096
#define OFF_AS   (OFF_WG + 64*64)       // 6*ACW
#define OFF_CS   (OFF_AS + 6*ACW)       // 6*ACW
#define SMEM_FLOATS (OFF_CS + 6*ACW)
#define SMEM_BYTES  (SMEM_FLOATS * 4)

__device__ __forceinline__ u64 pack2(float x, float y) {
    u64 r;
    asm("mov.b64 %0, {%1, %2};" : "=l"(r) : "f"(x), "f"(y));
    return r;
}
__device__ __forceinline__ void fma2(u64& d, u64 a, u64 b) {
    asm("fma.rn.f32x2 %0, %1, %2, %3;" : "=l"(d) : "l"(a), "l"(b), "l"(d));
}

__global__ __launch_bounds__(NTHREADS, 4)
void smf_fused_kernel(const float* __restrict__ X,
                      const float* __restrict__ Wg,
                      const float* __restrict__ bg,
                      const float* __restrict__ Wf,
                      const float* __restrict__ bf,
                      float* __restrict__ out)
{
    extern __shared__ float sm[];
    float* Xs  = sm + OFF_XS;   // [RS][PAD], rs = b*XR + j
    float* Vs  = sm + OFF_VS;   // [RS][PAD]
    float* Wgs = sm + OFF_WG;   // [64][64]
    float* As  = sm + OFF_AS;   // [(b*3+m)*ACW + j]
    float* Cs  = sm + OFF_CS;

    const int t  = threadIdx.x;
    const int r0 = blockIdx.x * TROWS;

    // ---- Phase A: stage X rows (both batches, wrap) + Wg ----
    {
        const float4* X4 = reinterpret_cast<const float4*>(X);
        #pragma unroll
        for (int idx = t; idx < RS * 16; idx += NTHREADS) {
            int rs = idx >> 4, q = idx & 15;
            int b  = rs >= XR;
            int j  = rs - b * XR;
            int gi = (r0 + j) & (Nc - 1);
            *reinterpret_cast<float4*>(&Xs[rs * PAD + q * 4]) =
                X4[((size_t)b * Nc + gi) * 16 + q];
        }
        const float4* Wg4 = reinterpret_cast<const float4*>(Wg);
        #pragma unroll
        for (int idx = t; idx < 64 * 16; idx += NTHREADS)
            *reinterpret_cast<float4*>(&Wgs[idx * 4]) = __ldg(Wg4 + idx);
    }
    __syncthreads();

    // ---- Phase B1: A/C dots (216 tasks), fully unrolled LDG (imm offsets) ----
    if (t < 216) {
        const int j = t % 18;
        const int g = t / 18;           // 0..11
        const int isC = g & 1;
        const int m   = (g >> 1) % 3;
        const int b   = g / 6;
        const int gic = (r0 + j + isC) & (Nc - 1);
        const float* wp = Wf + (size_t)m * Dc * Nc + gic;
        const float* xp = &Xs[(b * XR + j) * PAD];
        float acc0 = 0.f, acc1 = 0.f;
        #pragma unroll
        for (int d = 0; d < Dc; d += 2) {
            acc0 = fmaf(xp[d],     __ldg(wp + (size_t)d * Nc),       acc0);
            acc1 = fmaf(xp[d + 1], __ldg(wp + (size_t)(d + 1) * Nc), acc1);
        }
        float acc = acc0 + acc1 + __ldg(bf + m * Nc + gic);
        (isC ? Cs : As)[(b * 3 + m) * ACW + j] = acc;
    }

    // ---- Phase B2: GEMM V0 = X@Wg + bg ----
    // thread: cols [8g, 8g+8), rows {rg, 32+(rg>>2)} ; rg in 0..31.
    // Row 32+(rg>>2) is identical for the 4 rowgroups of a warp (LDS broadcast)
    // and computed redundantly by 4 threads (same value, same STS target).
    {
        const int g  = t & 7;
        const int rg = t >> 3;              // 0..31
        const int r2 = 32 + (rg >> 2);      // 32..39

        float4 bq0 = __ldg(reinterpret_cast<const float4*>(bg + 8 * g));
        float4 bq1 = __ldg(reinterpret_cast<const float4*>(bg + 8 * g + 4));
        u64 a0[4], a1[4];
        a0[0] = pack2(bq0.x, bq0.y);  a0[1] = pack2(bq0.z, bq0.w);
        a0[2] = pack2(bq1.x, bq1.y);  a0[3] = pack2(bq1.z, bq1.w);
        a1[0] = a0[0]; a1[1] = a0[1]; a1[2] = a0[2]; a1[3] = a0[3];

        const float* x0p = &Xs[rg * PAD];
        const float* x1p = &Xs[r2 * PAD];
        const float* wb  = &Wgs[8 * g];

        #pragma unroll
        for (int d = 0; d < Dc; d++) {
            const u64* wr = reinterpret_cast<const u64*>(wb + d * 64);
            u64 w0 = wr[0], w1 = wr[1], w2 = wr[2], w3 = wr[3];
            float x0 = x0p[d];
            u64 xx0 = pack2(x0, x0);
            fma2(a0[0], xx0, w0);  fma2(a0[1], xx0, w1);
            fma2(a0[2], xx0, w2);  fma2(a0[3], xx0, w3);
            float x1 = x1p[d];
            u64 xx1 = pack2(x1, x1);
            fma2(a1[0], xx1, w0);  fma2(a1[1], xx1, w1);
            fma2(a1[2], xx1, w2);  fma2(a1[3], xx1, w3);
        }

        ulonglong2* v0 = reinterpret_cast<ulonglong2*>(&Vs[rg * PAD + 8 * g]);
        v0[0] = make_ulonglong2(a0[0], a0[1]);
        v0[1] = make_ulonglong2(a0[2], a0[3]);
        ulonglong2* v1 = reinterpret_cast<ulonglong2*>(&Vs[r2 * PAD + 8 * g]);
        v1[0] = make_ulonglong2(a1[0], a1[1]);
        v1[1] = make_ulonglong2(a1[2], a1[3]);
    }
    __syncthreads();

    // ---- Phase C: inline weights + 4-tap combine + store ----
    {
        const int e0 = (t & 15) * 4;
        const int jr = t >> 4;
        #pragma unroll
        for (int b = 0; b < Bc; b++) {
            const float* A1 = &As[(b * 3 + 0) * ACW];
            const float* C1 = &Cs[(b * 3 + 0) * ACW];
            const float* A2 = &As[(b * 3 + 1) * ACW];
            const float* C2 = &Cs[(b * 3 + 1) * ACW];
            const float* A3p = &As[(b * 3 + 2) * ACW];
            const float* C3p = &Cs[(b * 3 + 2) * ACW];
            float A1i = A1[jr], A1i1 = A1[jr + 1], A1i2 = A1[jr + 2];
            float C1i = C1[jr], C1i1 = C1[jr + 1], C1i2 = C1[jr + 2];
            float A2i = A2[jr], A2i1 = A2[jr + 1];
            float C2i = C2[jr], C2i1 = C2[jr + 1];
            float A3  = A3p[jr], C3 = C3p[jr];
            float w0 = A3 * A2i * A1i;
            float w1 = A3 * (A2i * C1i + C2i * A1i1) + C3 * A2i1 * A1i1;
            float w2 = A3 * C2i * C1i1 + C3 * (A2i1 * C1i1 + C2i1 * A1i2);
            float w3 = C3 * C2i1 * C1i2;

            const float* vb = &Vs[(b * XR + jr) * PAD + e0];
            float4 p0 = *reinterpret_cast<const float4*>(vb);
            float4 p1 = *reinterpret_cast<const float4*>(vb + PAD);
            float4 p2 = *reinterpret_cast<const float4*>(vb + 2 * PAD);
            float4 p3 = *reinterpret_cast<const float4*>(vb + 3 * PAD);

            float4 o;
            o.x = w0 * p0.x + w1 * p1.x + w2 * p2.x + w3 * p3.x;
            o.y = w0 * p0.y + w1 * p1.y + w2 * p2.y + w3 * p3.y;
            o.z = w0 * p0.z + w1 * p1.z + w2 * p2.z + w3 * p3.z;
            o.w = w0 * p0.w + w1 * p1.w + w2 * p2.w + w3 * p3.w;

            const int gi = r0 + jr;
            *reinterpret_cast<float4*>(&out[((size_t)b * Nc + gi) * 64 + e0]) = o;
        }
    }
}

extern "C" void kernel_launch(void* const* d_in, const int* in_sizes, int n_in,
                              void* d_out, int out_size)
{
    const float* X  = (const float*)d_in[0];   // (2, 8192, 64)
    const float* Wg = (const float*)d_in[1];   // (64, 64)
    const float* bg = (const float*)d_in[2];   // (64,)
    const float* Wf = (const float*)d_in[3];   // (3, 64, 8192)
    const float* bf = (const float*)d_in[4];   // (3, 8192)
    float* out = (float*)d_out;                // (2, 8192, 64)

    cudaFuncSetAttribute(smf_fused_kernel,
                         cudaFuncAttributeMaxDynamicSharedMemorySize, SMEM_BYTES);

    dim3 grid(Nc / TROWS, 1);                  // 512 CTAs
    smf_fused_kernel<<<grid, NTHREADS, SMEM_BYTES>>>(X, Wg, bg, Wf, bf, out);
}

// round 10
// speedup vs baseline: 1.3741x; 1.3741x over previous
#include <cuda_runtime.h>

// SMFNet B=2,N=8192,D=64,DV=64,M=3 — chord mask = diag + superdiag(wrap).
// out = S · V0 ;  V0 = X@Wg + bg ; S = product of three 2-banded chord mats:
//   out[i] = w0 V0[i] + w1 V0[i+1] + w2 V0[i+2] + w3 V0[i+3]   (wrap)
//   Am_j = X[j]·Wf[m][:,j] + bf[m][j],  Cm_j = X[j]·Wf[m][:,j+1] + bf[m][j+1]
// R10: 61 output rows/CTA (64 staged, halo amortized), one batch per CTA,
// grid (135,2). GEMM: balanced 2row x 8col/thread, dup-x smem + smem Wg,
// 12 instr / 16 FMA per d. A/C: 6 series x 64 j, warps 0-3 dual-interleaved.

#define Nc   8192
#define Dc   64
#define TROWS 61
#define RS    64           // staged row slots
#define XDP   66           // Xd row stride in u64
#define VPAD  68           // Vs row stride in floats
#define ACP   66           // AC row stride
#define NTHREADS 256

typedef unsigned long long u64;

// smem floats: Xd 64*66*2=8448, Wgs 4096, Vs 64*68=4352, AC 6*66=396
#define OFF_WG   (RS*XDP*2)
#define OFF_VS   (OFF_WG + 64*64)
#define OFF_AC   (OFF_VS + RS*VPAD)
#define SMEM_FLOATS (OFF_AC + 6*ACP)
#define SMEM_BYTES  (SMEM_FLOATS * 4)

__device__ __forceinline__ u64 pack2(float x, float y) {
    u64 r;
    asm("mov.b64 %0, {%1, %2};" : "=l"(r) : "f"(x), "f"(y));
    return r;
}
__device__ __forceinline__ void fma2(u64& d, u64 a, u64 b) {
    asm("fma.rn.f32x2 %0, %1, %2, %3;" : "=l"(d) : "l"(a), "l"(b), "l"(d));
}

__global__ __launch_bounds__(NTHREADS, 3)
void smf_fused_kernel(const float* __restrict__ X,
                      const float* __restrict__ Wg,
                      const float* __restrict__ bg,
                      const float* __restrict__ Wf,
                      const float* __restrict__ bf,
                      float* __restrict__ out)
{
    extern __shared__ float sm[];
    u64*   Xd  = reinterpret_cast<u64*>(sm);   // [RS][XDP], (x,x) pairs
    float* Wgs = sm + OFF_WG;                  // [64][64]
    float* Vs  = sm + OFF_VS;                  // [RS][VPAD]
    float* AC  = sm + OFF_AC;                  // [6][ACP]; s = m*2 + isC

    const int t  = threadIdx.x;
    const int b  = blockIdx.y;
    const int r0 = blockIdx.x * TROWS;

    // ---- Phase A: stage X (duplicated pairs) + Wg ----
    {
        const float4* X4 = reinterpret_cast<const float4*>(X);
        #pragma unroll
        for (int idx = t; idx < RS * 16; idx += NTHREADS) {
            int rs = idx >> 4, q = idx & 15;
            int gi = (r0 + rs) & (Nc - 1);
            float4 v = __ldg(X4 + ((size_t)b * Nc + gi) * 16 + q);
            u64* dst = Xd + rs * XDP + q * 4;
            dst[0] = pack2(v.x, v.x);
            dst[1] = pack2(v.y, v.y);
            dst[2] = pack2(v.z, v.z);
            dst[3] = pack2(v.w, v.w);
        }
        const float4* Wg4 = reinterpret_cast<const float4*>(Wg);
        #pragma unroll
        for (int idx = t; idx < 64 * 16; idx += NTHREADS)
            *reinterpret_cast<float4*>(&Wgs[idx * 4]) = __ldg(Wg4 + idx);
    }
    __syncthreads();

    // ---- Phase B1: A/C dots. series s = m*2+isC; warps 0-3: s0∈{0,1}+s1∈{4,5};
    //      warps 4-7: s0∈{2,3}. x read from low halves of Xd. ----
    {
        const int j  = t & 63;
        const int s0 = t >> 6;                       // 0..3
        const int m0 = s0 >> 1, c0 = s0 & 1;
        const int g0 = (r0 + j + c0) & (Nc - 1);
        const float* w0 = Wf + (size_t)m0 * Dc * Nc + g0;
        const float* xp = reinterpret_cast<const float*>(Xd + j * XDP);
        float a0a = 0.f, a0b = 0.f;
        if (t < 128) {
            const int s1 = 4 + (t >> 6);             // 4..5
            const int c1 = s1 & 1;
            const int g1 = (r0 + j + c1) & (Nc - 1);
            const float* w1 = Wf + (size_t)2 * Dc * Nc + g1;
            float a1a = 0.f, a1b = 0.f;
            #pragma unroll
            for (int d = 0; d < Dc; d += 2) {
                float x0 = xp[2 * d], x1 = xp[2 * (d + 1)];
                a0a = fmaf(x0, __ldg(w0 + (size_t)d * Nc), a0a);
                a1a = fmaf(x0, __ldg(w1 + (size_t)d * Nc), a1a);
                a0b = fmaf(x1, __ldg(w0 + (size_t)(d + 1) * Nc), a0b);
                a1b = fmaf(x1, __ldg(w1 + (size_t)(d + 1) * Nc), a1b);
            }
            AC[s1 * ACP + j] = a1a + a1b + __ldg(bf + 2 * Nc + g1);
        } else {
            #pragma unroll
            for (int d = 0; d < Dc; d += 2) {
                a0a = fmaf(xp[2 * d],       __ldg(w0 + (size_t)d * Nc),       a0a);
                a0b = fmaf(xp[2 * (d + 1)], __ldg(w0 + (size_t)(d + 1) * Nc), a0b);
            }
        }
        AC[s0 * ACP + j] = a0a + a0b + __ldg(bf + m0 * Nc + g0);
    }

    // ---- Phase B2: GEMM V0 = X@Wg + bg. 2 rows x 8 cols per thread. ----
    {
        const int cg = t & 7;          // col group: cols [8cg, 8cg+8)
        const int rg = t >> 3;         // rows rg, rg+32
        const u64* x0p = Xd + rg * XDP;
        const u64* x1p = Xd + (rg + 32) * XDP;
        const float* wp = Wgs + cg * 8;

        float4 bq0 = __ldg(reinterpret_cast<const float4*>(bg + cg * 8));
        float4 bq1 = __ldg(reinterpret_cast<const float4*>(bg + cg * 8 + 4));
        u64 a0[4], a1[4];
        a0[0] = pack2(bq0.x, bq0.y);  a0[1] = pack2(bq0.z, bq0.w);
        a0[2] = pack2(bq1.x, bq1.y);  a0[3] = pack2(bq1.z, bq1.w);
        a1[0] = a0[0]; a1[1] = a0[1]; a1[2] = a0[2]; a1[3] = a0[3];

        #pragma unroll 8
        for (int d = 0; d < Dc; d++) {
            u64 x0 = x0p[d];
            u64 x1 = x1p[d];
            ulonglong2 wA = *reinterpret_cast<const ulonglong2*>(wp + d * 64);
            ulonglong2 wB = *reinterpret_cast<const ulonglong2*>(wp + d * 64 + 4);
            fma2(a0[0], x0, wA.x);  fma2(a0[1], x0, wA.y);
            fma2(a0[2], x0, wB.x);  fma2(a0[3], x0, wB.y);
            fma2(a1[0], x1, wA.x);  fma2(a1[1], x1, wA.y);
            fma2(a1[2], x1, wB.x);  fma2(a1[3], x1, wB.y);
        }
        ulonglong2* v0 = reinterpret_cast<ulonglong2*>(&Vs[rg * VPAD + cg * 8]);
        v0[0] = make_ulonglong2(a0[0], a0[1]);
        v0[1] = make_ulonglong2(a0[2], a0[3]);
        ulonglong2* v1 = reinterpret_cast<ulonglong2*>(&Vs[(rg + 32) * VPAD + cg * 8]);
        v1[0] = make_ulonglong2(a1[0], a1[1]);
        v1[1] = make_ulonglong2(a1[2], a1[3]);
    }
    __syncthreads();

    // ---- Phase C: inline weights + 4-tap combine + store (61*16 tasks) ----
    for (int task = t; task < TROWS * 16; task += NTHREADS) {
        const int jr = task >> 4;
        const int e0 = (task & 15) * 4;

        float A1i = AC[0 * ACP + jr], A1i1 = AC[0 * ACP + jr + 1], A1i2 = AC[0 * ACP + jr + 2];
        float C1i = AC[1 * ACP + jr], C1i1 = AC[1 * ACP + jr + 1], C1i2 = AC[1 * ACP + jr + 2];
        float A2i = AC[2 * ACP + jr], A2i1 = AC[2 * ACP + jr + 1];
        float C2i = AC[3 * ACP + jr], C2i1 = AC[3 * ACP + jr + 1];
        float A3  = AC[4 * ACP + jr], C3   = AC[5 * ACP + jr];
        float w0 = A3 * A2i * A1i;
        float w1 = A3 * (A2i * C1i + C2i * A1i1) + C3 * A2i1 * A1i1;
        float w2 = A3 * C2i * C1i1 + C3 * (A2i1 * C1i1 + C2i1 * A1i2);
        float w3 = C3 * C2i1 * C1i2;

        const float* vb = &Vs[jr * VPAD + e0];
        float4 p0 = *reinterpret_cast<const float4*>(vb);
        float4 p1 = *reinterpret_cast<const float4*>(vb + VPAD);
        float4 p2 = *reinterpret_cast<const float4*>(vb + 2 * VPAD);
        float4 p3 = *reinterpret_cast<const float4*>(vb + 3 * VPAD);

        float4 o;
        o.x = w0 * p0.x + w1 * p1.x + w2 * p2.x + w3 * p3.x;
        o.y = w0 * p0.y + w1 * p1.y + w2 * p2.y + w3 * p3.y;
        o.z = w0 * p0.z + w1 * p1.z + w2 * p2.z + w3 * p3.z;
        o.w = w0 * p0.w + w1 * p1.w + w2 * p2.w + w3 * p3.w;

        const int gi = (r0 + jr) & (Nc - 1);
        *reinterpret_cast<float4*>(&out[((size_t)b * Nc + gi) * 64 + e0]) = o;
    }
}

extern "C" void kernel_launch(void* const* d_in, const int* in_sizes, int n_in,
                              void* d_out, int out_size)
{
    const float* X  = (const float*)d_in[0];   // (2, 8192, 64)
    const float* Wg = (const float*)d_in[1];   // (64, 64)
    const float* bg = (const float*)d_in[2];   // (64,)
    const float* Wf = (const float*)d_in[3];   // (3, 64, 8192)
    const float* bf = (const float*)d_in[4];   // (3, 8192)
    float* out = (float*)d_out;                // (2, 8192, 64)

    cudaFuncSetAttribute(smf_fused_kernel,
                         cudaFuncAttributeMaxDynamicSharedMemorySize, SMEM_BYTES);

    dim3 grid((Nc + TROWS - 1) / TROWS, 2);    // (135, 2) = 270 CTAs
    smf_fused_kernel<<<grid, NTHREADS, SMEM_BYTES>>>(X, Wg, bg, Wf, bf, out);
}

// round 11
// speedup vs baseline: 1.6996x; 1.2369x over previous
#include <cuda_runtime.h>

// SMFNet B=2,N=8192,D=64,DV=64,M=3 — chord mask = diag + superdiag(wrap).
// out = S · V0 ;  V0 = X@Wg + bg ; S = product of three 2-banded chord mats:
//   out[i] = w0 V0[i] + w1 V0[i+1] + w2 V0[i+2] + w3 V0[i+3]   (wrap)
//   Am_j = X[j]·Wf[m][:,j] + bf[m][j],  Cm_j = X[j]·Wf[m][:,j+1] + bf[m][j+1]
// R11 = R6 + column-shared A/C: w[:,i] serves both A[i] (X[i]) and C[i-1]
// (X[i-1]) -> half the Wf loads of R6.

#define Bc   2
#define Nc   8192
#define Dc   64
#define TROWS 16           // output rows per CTA  -> 512 CTAs
#define XR    19           // staged rows per batch (TROWS + 3 halo)
#define RS    (2*XR)       // row-slots (both batches) = 38
#define PAD   68           // float4-aligned row stride
#define ACW   20           // A/C stride per (b,m)
#define NTHREADS 256

#define OFF_XS  0                      // RS*PAD = 2584
#define OFF_VS  (OFF_XS + RS*PAD)      // RS*PAD = 2584
#define OFF_AS  (OFF_VS + RS*PAD)      // 6*ACW
#define OFF_CS  (OFF_AS + 6*ACW)       // 6*ACW
#define SMEM_FLOATS (OFF_CS + 6*ACW)
#define SMEM_BYTES  (SMEM_FLOATS * 4)

typedef unsigned long long u64;

__device__ __forceinline__ u64 pack2(float x, float y) {
    u64 r;
    asm("mov.b64 %0, {%1, %2};" : "=l"(r) : "f"(x), "f"(y));
    return r;
}
__device__ __forceinline__ void unpack2(u64 v, float& x, float& y) {
    asm("mov.b64 {%0, %1}, %2;" : "=f"(x), "=f"(y) : "l"(v));
}
__device__ __forceinline__ void fma2(u64& d, u64 a, u64 b) {
    asm("fma.rn.f32x2 %0, %1, %2, %3;" : "=l"(d) : "l"(a), "l"(b), "l"(d));
}

__global__ __launch_bounds__(NTHREADS, 4)
void smf_fused_kernel(const float* __restrict__ X,
                      const float* __restrict__ Wg,
                      const float* __restrict__ bg,
                      const float* __restrict__ Wf,
                      const float* __restrict__ bf,
                      float* __restrict__ out)
{
    extern __shared__ float sm[];
    float* Xs = sm + OFF_XS;   // [RS][PAD], rs = b*XR + j
    float* Vs = sm + OFF_VS;   // [RS][PAD]
    float* As = sm + OFF_AS;   // [(b*3+m)*ACW + j]
    float* Cs = sm + OFF_CS;

    const int t  = threadIdx.x;
    const int r0 = blockIdx.x * TROWS;

    // ---- Phase A: stage X rows r0..r0+18 (wrap) for both batches ----
    {
        const float4* X4 = reinterpret_cast<const float4*>(X);
        #pragma unroll
        for (int idx = t; idx < RS * 16; idx += NTHREADS) {
            int rs = idx >> 4, q = idx & 15;
            int b  = rs >= XR;
            int j  = rs - b * XR;
            int gi = (r0 + j) & (Nc - 1);
            *reinterpret_cast<float4*>(&Xs[rs * PAD + q * 4]) =
                X4[((size_t)b * Nc + gi) * 16 + q];
        }
    }
    __syncthreads();

    // ---- Phase B1: column-shared A/C dots. 114 tasks = 19 cols x 3m x 2b.
    //      Column gi = r0+c serves A[c] (X[c]) and C[c-1] (X[c-1]). ----
    if (t < 114) {
        const int c = t % 19;
        const int g = t / 19;           // 0..5
        const int m = g % 3;
        const int b = g / 3;
        const int gi  = (r0 + c) & (Nc - 1);
        const int cm1 = (c == 0) ? 0 : (c - 1);   // c==0: C discarded
        const float* wp = Wf + (size_t)m * Dc * Nc + gi;
        const float* xA = &Xs[(b * XR + c)   * PAD];
        const float* xC = &Xs[(b * XR + cm1) * PAD];
        float aA0 = 0.f, aA1 = 0.f, aC0 = 0.f, aC1 = 0.f;
        #pragma unroll 16
        for (int d = 0; d < Dc; d += 2) {
            float w0 = __ldg(wp + (size_t)d * Nc);
            float w1 = __ldg(wp + (size_t)(d + 1) * Nc);
            aA0 = fmaf(xA[d],     w0, aA0);
            aA1 = fmaf(xA[d + 1], w1, aA1);
            aC0 = fmaf(xC[d],     w0, aC0);
            aC1 = fmaf(xC[d + 1], w1, aC1);
        }
        const float bfv = __ldg(bf + m * Nc + gi);
        if (c < 18) As[(b * 3 + m) * ACW + c] = aA0 + aA1 + bfv;
        if (c >= 1) Cs[(b * 3 + m) * ACW + (c - 1)] = aC0 + aC1 + bfv;
    }

    // ---- Phase B2: GEMM V0 = X@Wg + bg for all 38 row-slots ----
    // thread: col quad e0 = 4*(t&15); row-slots rsb, rsb+16, (+32 if <38)
    {
        const int e0  = (t & 15) * 4;
        const int rsb = t >> 4;
        float4 bgq = __ldg(reinterpret_cast<const float4*>(bg + e0));
        u64 a0_01 = pack2(bgq.x, bgq.y), a0_23 = pack2(bgq.z, bgq.w);
        u64 a1_01 = a0_01, a1_23 = a0_23;
        u64 a2_01 = a0_01, a2_23 = a0_23;
        const bool has3 = (rsb < RS - 32);     // rsb < 6 — uniform per warp

        #pragma unroll 8
        for (int d = 0; d < Dc; d++) {
            float4 wv = __ldg(reinterpret_cast<const float4*>(Wg + d * 64 + e0));
            u64 w01 = pack2(wv.x, wv.y);
            u64 w23 = pack2(wv.z, wv.w);
            float x0 = Xs[ rsb       * PAD + d];
            float x1 = Xs[(rsb + 16) * PAD + d];
            u64 xx0 = pack2(x0, x0);
            u64 xx1 = pack2(x1, x1);
            fma2(a0_01, xx0, w01);  fma2(a0_23, xx0, w23);
            fma2(a1_01, xx1, w01);  fma2(a1_23, xx1, w23);
            if (has3) {
                float x2 = Xs[(rsb + 32) * PAD + d];
                u64 xx2 = pack2(x2, x2);
                fma2(a2_01, xx2, w01);  fma2(a2_23, xx2, w23);
            }
        }
        float v0, v1, v2, v3;
        unpack2(a0_01, v0, v1); unpack2(a0_23, v2, v3);
        *reinterpret_cast<float4*>(&Vs[rsb * PAD + e0]) = make_float4(v0, v1, v2, v3);
        unpack2(a1_01, v0, v1); unpack2(a1_23, v2, v3);
        *reinterpret_cast<float4*>(&Vs[(rsb + 16) * PAD + e0]) = make_float4(v0, v1, v2, v3);
        if (has3) {
            unpack2(a2_01, v0, v1); unpack2(a2_23, v2, v3);
            *reinterpret_cast<float4*>(&Vs[(rsb + 32) * PAD + e0]) = make_float4(v0, v1, v2, v3);
        }
    }
    __syncthreads();

    // ---- Phase C: inline weights + 4-tap combine + store ----
    {
        const int e0 = (t & 15) * 4;
        const int jr = t >> 4;
        #pragma unroll
        for (int b = 0; b < Bc; b++) {
            const float* A1 = &As[(b * 3 + 0) * ACW];
            const float* C1 = &Cs[(b * 3 + 0) * ACW];
            const float* A2 = &As[(b * 3 + 1) * ACW];
            const float* C2 = &Cs[(b * 3 + 1) * ACW];
            const float* A3p = &As[(b * 3 + 2) * ACW];
            const float* C3p = &Cs[(b * 3 + 2) * ACW];
            float A1i = A1[jr], A1i1 = A1[jr + 1], A1i2 = A1[jr + 2];
            float C1i = C1[jr], C1i1 = C1[jr + 1], C1i2 = C1[jr + 2];
            float A2i = A2[jr], A2i1 = A2[jr + 1];
            float C2i = C2[jr], C2i1 = C2[jr + 1];
            float A3  = A3p[jr], C3 = C3p[jr];
            float w0 = A3 * A2i * A1i;
            float w1 = A3 * (A2i * C1i + C2i * A1i1) + C3 * A2i1 * A1i1;
            float w2 = A3 * C2i * C1i1 + C3 * (A2i1 * C1i1 + C2i1 * A1i2);
            float w3 = C3 * C2i1 * C1i2;

            const float* vb = &Vs[(b * XR + jr) * PAD + e0];
            float4 p0 = *reinterpret_cast<const float4*>(vb);
            float4 p1 = *reinterpret_cast<const float4*>(vb + PAD);
            float4 p2 = *reinterpret_cast<const float4*>(vb + 2 * PAD);
            float4 p3 = *reinterpret_cast<const float4*>(vb + 3 * PAD);

            float4 o;
            o.x = w0 * p0.x + w1 * p1.x + w2 * p2.x + w3 * p3.x;
            o.y = w0 * p0.y + w1 * p1.y + w2 * p2.y + w3 * p3.y;
            o.z = w0 * p0.z + w1 * p1.z + w2 * p2.z + w3 * p3.z;
            o.w = w0 * p0.w + w1 * p1.w + w2 * p2.w + w3 * p3.w;

            const int gi = r0 + jr;
            *reinterpret_cast<float4*>(&out[((size_t)b * Nc + gi) * 64 + e0]) = o;
        }
    }
}

extern "C" void kernel_launch(void* const* d_in, const int* in_sizes, int n_in,
                              void* d_out, int out_size)
{
    const float* X  = (const float*)d_in[0];   // (2, 8192, 64)
    const float* Wg = (const float*)d_in[1];   // (64, 64)
    const float* bg = (const float*)d_in[2];   // (64,)
    const float* Wf = (const float*)d_in[3];   // (3, 64, 8192)
    const float* bf = (const float*)d_in[4];   // (3, 8192)
    float* out = (float*)d_out;                // (2, 8192, 64)

    cudaFuncSetAttribute(smf_fused_kernel,
                         cudaFuncAttributeMaxDynamicSharedMemorySize, SMEM_BYTES);

    dim3 grid(Nc / TROWS, 1);                  // 512 CTAs
    smf_fused_kernel<<<grid, NTHREADS, SMEM_BYTES>>>(X, Wg, bg, Wf, bf, out);
}

// round 12
// speedup vs baseline: 1.7060x; 1.0037x over previous
#include <cuda_runtime.h>

// SMFNet B=2,N=8192,D=64,DV=64,M=3 — chord mask = diag + superdiag(wrap).
// out = S · V0 ;  V0 = X@Wg + bg ;
//   out[i] = w0 V0[i] + w1 V0[i+1] + w2 V0[i+2] + w3 V0[i+3]   (wrap)
//   Am_j = X[j]·Wf[m][:,j] + bf[m][j],  Cm_j = X[j]·Wf[m][:,j+1] + bf[m][j+1]
// R12: 1024 small CTAs (128 thr, one batch, 8/SM) to desynchronize barrier
// groups; smem Wg with LDS.128 pairs (no packs/LDG in GEMM loop);
// column-shared A/C on warps 0-1, 3-row GEMM tiles on warps 2-3.

#define Nc   8192
#define Dc   64
#define TROWS 16
#define XR    20           // staged rows (16 + 3 halo + 1 pad, wrap)
#define PAD   68           // float4-aligned row stride (272B)
#define ACW   20
#define NTHREADS 128

typedef unsigned long long u64;

// smem (floats)
#define OFF_XS  0                     // XR*PAD = 1360
#define OFF_VS  (OFF_XS + XR*PAD)     // 1360  (byte 5440, 16B-aligned)
#define OFF_WG  (OFF_VS + XR*PAD)     // 4096  (byte 10880, 16B-aligned)
#define OFF_AS  (OFF_WG + 64*64)      // 3*ACW
#define OFF_CS  (OFF_AS + 3*ACW)      // 3*ACW
#define SMEM_FLOATS (OFF_CS + 3*ACW)
#define SMEM_BYTES  (SMEM_FLOATS * 4)

__device__ __forceinline__ u64 pack2(float x, float y) {
    u64 r;
    asm("mov.b64 %0, {%1, %2};" : "=l"(r) : "f"(x), "f"(y));
    return r;
}
__device__ __forceinline__ void fma2(u64& d, u64 a, u64 b) {
    asm("fma.rn.f32x2 %0, %1, %2, %3;" : "=l"(d) : "l"(a), "l"(b), "l"(d));
}

__global__ __launch_bounds__(NTHREADS, 8)
void smf_fused_kernel(const float* __restrict__ X,
                      const float* __restrict__ Wg,
                      const float* __restrict__ bg,
                      const float* __restrict__ Wf,
                      const float* __restrict__ bf,
                      float* __restrict__ out)
{
    extern __shared__ float sm[];
    float* Xs  = sm + OFF_XS;   // [XR][PAD]
    float* Vs  = sm + OFF_VS;   // [XR][PAD]
    float* Wgs = sm + OFF_WG;   // [64][64]
    float* As  = sm + OFF_AS;   // [m*ACW + j]
    float* Cs  = sm + OFF_CS;

    const int t  = threadIdx.x;
    const int b  = blockIdx.y;
    const int r0 = blockIdx.x * TROWS;

    // ---- Phase A: stage X rows r0..r0+19 (wrap) + Wg ----
    {
        const float4* X4 = reinterpret_cast<const float4*>(X + (size_t)b * Nc * Dc);
        #pragma unroll
        for (int idx = t; idx < XR * 16; idx += NTHREADS) {
            int rs = idx >> 4, q = idx & 15;
            int gi = (r0 + rs) & (Nc - 1);
            *reinterpret_cast<float4*>(&Xs[rs * PAD + q * 4]) = __ldg(X4 + gi * 16 + q);
        }
        const float4* Wg4 = reinterpret_cast<const float4*>(Wg);
        #pragma unroll
        for (int idx = t; idx < 64 * 16; idx += NTHREADS)
            *reinterpret_cast<float4*>(&Wgs[idx * 4]) = __ldg(Wg4 + idx);
    }
    __syncthreads();

    // ---- Phase B1 (warps 0-1): column-shared A/C dots, 57 tasks ----
    // Column gi=r0+c serves A[c] (X[c]) and C[c-1] (X[c-1]).
    if (t < 57) {
        const int c = t % 19;
        const int m = t / 19;           // 0..2
        const int gi  = (r0 + c) & (Nc - 1);
        const int cm1 = (c == 0) ? 0 : (c - 1);
        const float* wp = Wf + (size_t)m * Dc * Nc + gi;
        const float* xA = &Xs[c   * PAD];
        const float* xC = &Xs[cm1 * PAD];
        float aA0 = 0.f, aA1 = 0.f, aC0 = 0.f, aC1 = 0.f;
        #pragma unroll 16
        for (int d = 0; d < Dc; d += 2) {
            float w0 = __ldg(wp + (size_t)d * Nc);
            float w1 = __ldg(wp + (size_t)(d + 1) * Nc);
            aA0 = fmaf(xA[d],     w0, aA0);
            aA1 = fmaf(xA[d + 1], w1, aA1);
            aC0 = fmaf(xC[d],     w0, aC0);
            aC1 = fmaf(xC[d + 1], w1, aC1);
        }
        const float bfv = __ldg(bf + m * Nc + gi);
        if (c < 18) As[m * ACW + c] = aA0 + aA1 + bfv;
        if (c >= 1) Cs[m * ACW + (c - 1)] = aC0 + aC1 + bfv;
    }

    // ---- Phase B2 (all threads): GEMM V0 = X@Wg + bg, 20 row slots ----
    // thread: cols [e0,e0+4); rows rg, rg+8; warps 2-3 (rg>=4) add row 12+rg.
    {
        const int e0 = (t & 15) * 4;
        const int rg = t >> 4;              // 0..7
        const bool has3 = (rg >= 4);        // rows 16..19 on warps 2-3
        const int r2 = 12 + rg;

        float4 bq = __ldg(reinterpret_cast<const float4*>(bg + e0));
        u64 a0x = pack2(bq.x, bq.y), a0y = pack2(bq.z, bq.w);
        u64 a1x = a0x, a1y = a0y;
        u64 a2x = a0x, a2y = a0y;

        const float* x0p = &Xs[rg * PAD];
        const float* x1p = &Xs[(rg + 8) * PAD];
        const float* x2p = &Xs[r2 * PAD];
        const float* wp  = &Wgs[e0];

        #pragma unroll 8
        for (int d = 0; d < Dc; d++) {
            ulonglong2 w = *reinterpret_cast<const ulonglong2*>(wp + d * 64);
            float x0 = x0p[d];
            u64 xx0 = pack2(x0, x0);
            fma2(a0x, xx0, w.x);  fma2(a0y, xx0, w.y);
            float x1 = x1p[d];
            u64 xx1 = pack2(x1, x1);
            fma2(a1x, xx1, w.x);  fma2(a1y, xx1, w.y);
            if (has3) {
                float x2 = x2p[d];
                u64 xx2 = pack2(x2, x2);
                fma2(a2x, xx2, w.x);  fma2(a2y, xx2, w.y);
            }
        }
        *reinterpret_cast<ulonglong2*>(&Vs[rg * PAD + e0])       = make_ulonglong2(a0x, a0y);
        *reinterpret_cast<ulonglong2*>(&Vs[(rg + 8) * PAD + e0]) = make_ulonglong2(a1x, a1y);
        if (has3)
            *reinterpret_cast<ulonglong2*>(&Vs[r2 * PAD + e0])   = make_ulonglong2(a2x, a2y);
    }
    __syncthreads();

    // ---- Phase C: inline weights + 4-tap combine + store (256 tasks) ----
    #pragma unroll
    for (int task = t; task < TROWS * 16; task += NTHREADS) {
        const int jr = task >> 4;
        const int e0 = (task & 15) * 4;

        float A1i = As[0 * ACW + jr], A1i1 = As[0 * ACW + jr + 1], A1i2 = As[0 * ACW + jr + 2];
        float C1i = Cs[0 * ACW + jr], C1i1 = Cs[0 * ACW + jr + 1], C1i2 = Cs[0 * ACW + jr + 2];
        float A2i = As[1 * ACW + jr], A2i1 = As[1 * ACW + jr + 1];
        float C2i = Cs[1 * ACW + jr], C2i1 = Cs[1 * ACW + jr + 1];
        float A3  = As[2 * ACW + jr], C3   = Cs[2 * ACW + jr];
        float w0 = A3 * A2i * A1i;
        float w1 = A3 * (A2i * C1i + C2i * A1i1) + C3 * A2i1 * A1i1;
        float w2 = A3 * C2i * C1i1 + C3 * (A2i1 * C1i1 + C2i1 * A1i2);
        float w3 = C3 * C2i1 * C1i2;

        const float* vb = &Vs[jr * PAD + e0];
        float4 p0 = *reinterpret_cast<const float4*>(vb);
        float4 p1 = *reinterpret_cast<const float4*>(vb + PAD);
        float4 p2 = *reinterpret_cast<const float4*>(vb + 2 * PAD);
        float4 p3 = *reinterpret_cast<const float4*>(vb + 3 * PAD);

        float4 o;
        o.x = w0 * p0.x + w1 * p1.x + w2 * p2.x + w3 * p3.x;
        o.y = w0 * p0.y + w1 * p1.y + w2 * p2.y + w3 * p3.y;
        o.z = w0 * p0.z + w1 * p1.z + w2 * p2.z + w3 * p3.z;
        o.w = w0 * p0.w + w1 * p1.w + w2 * p2.w + w3 * p3.w;

        const int gi = r0 + jr;
        *reinterpret_cast<float4*>(&out[((size_t)b * Nc + gi) * 64 + e0]) = o;
    }
}

extern "C" void kernel_launch(void* const* d_in, const int* in_sizes, int n_in,
                              void* d_out, int out_size)
{
    const float* X  = (const float*)d_in[0];   // (2, 8192, 64)
    const float* Wg = (const float*)d_in[1];   // (64, 64)
    const float* bg = (const float*)d_in[2];   // (64,)
    const float* Wf = (const float*)d_in[3];   // (3, 64, 8192)
    const float* bf = (const float*)d_in[4];   // (3, 8192)
    float* out = (float*)d_out;                // (2, 8192, 64)

    cudaFuncSetAttribute(smf_fused_kernel,
                         cudaFuncAttributeMaxDynamicSharedMemorySize, SMEM_BYTES);

    dim3 grid(Nc / TROWS, 2);                  // (512, 2) = 1024 CTAs
    smf_fused_kernel<<<grid, NTHREADS, SMEM_BYTES>>>(X, Wg, bg, Wf, bf, out);
}